// round 2
// baseline (speedup 1.0000x reference)
#include <cuda_runtime.h>

// ---------------- problem constants ----------------
#define B_  4
#define C_  2304
#define N_  2304          // H*W
#define E_  2304
#define HW  48
#define PW  50            // padded width (48 + 2)
#define NH_ 4
#define K2  20736         // C_*9, conv2 GEMM K
#define E2  4608          // 2*E

// ---------------- device scratch (static, allowed) ----------------
__device__ float g_hp  [(size_t)B_ * C_ * PW * PW];   // padded relu(conv1) : 92 MB
__device__ float g_down[(size_t)B_ * C_ * N_];
__device__ float g_q   [(size_t)B_ * C_ * N_];
__device__ float g_k   [(size_t)B_ * C_ * N_];
__device__ float g_v   [(size_t)B_ * C_ * N_];
__device__ float g_qk  [(size_t)B_ * C_ * N_];        // also attn (in place)
__device__ float g_ao  [(size_t)B_ * C_ * N_];
__device__ float g_h1  [(size_t)B_ * C_ * N_];
__device__ float g_mid [(size_t)B_ * N_ * E2];        // FFN hidden : 170 MB
__device__ float g_f   [(size_t)B_ * C_ * N_];

// ---------------- block reductions ----------------
__device__ __forceinline__ float block_sum(float v, float* red) {
    int tid = threadIdx.x;
    red[tid] = v; __syncthreads();
    #pragma unroll
    for (int s = 128; s > 0; s >>= 1) {
        if (tid < s) red[tid] += red[tid + s];
        __syncthreads();
    }
    float r = red[0]; __syncthreads();
    return r;
}
__device__ __forceinline__ float block_max(float v, float* red) {
    int tid = threadIdx.x;
    red[tid] = v; __syncthreads();
    #pragma unroll
    for (int s = 128; s > 0; s >>= 1) {
        if (tid < s) red[tid] = fmaxf(red[tid], red[tid + s]);
        __syncthreads();
    }
    float r = red[0]; __syncthreads();
    return r;
}

// ---------------- conv1 (3x3, 1->C) + ReLU, written zero-padded ----------------
__global__ void conv1_relu_pad(const float* __restrict__ x, const float* __restrict__ w,
                               const float* __restrict__ bia, float* __restrict__ hp) {
    int idx = blockIdx.x * 256 + threadIdx.x;            // total = 4*2304*2500 = 90000*256
    int b   = idx / (C_ * PW * PW);
    int rem = idx - b * (C_ * PW * PW);
    int c   = rem / (PW * PW);
    int p   = rem - c * (PW * PW);
    int yy  = p / PW, xx = p - yy * PW;
    float out = 0.f;
    if (yy >= 1 && yy <= HW && xx >= 1 && xx <= HW) {
        int y = yy - 1, x0 = xx - 1;
        float acc = bia[c];
        const float* xb = x + b * HW * HW;
        #pragma unroll
        for (int ky = 0; ky < 3; ky++) {
            int iy = y + ky - 1;
            if (iy < 0 || iy >= HW) continue;
            #pragma unroll
            for (int kx = 0; kx < 3; kx++) {
                int ix = x0 + kx - 1;
                if (ix < 0 || ix >= HW) continue;
                acc += w[c * 9 + ky * 3 + kx] * xb[iy * HW + ix];
            }
        }
        out = fmaxf(acc, 0.f);
    }
    hp[idx] = out;
}

// ---------------- generic 128x128x16 SGEMM ----------------
// BIAS_MODE: 0 none, 1 per-row (bias[m]), 2 per-col (bias[n]). TRANSB: B stored (N,K) row-major.
template<int BIAS_MODE, bool RELU, bool TRANSB>
__global__ void __launch_bounds__(256) sgemm(const float* __restrict__ A,
                                             const float* __restrict__ Bm,
                                             float* __restrict__ Cm,
                                             const float* __restrict__ bias,
                                             int M, int N, int K,
                                             long long sA, long long sB, long long sC) {
    __shared__ float As[16][128];
    __shared__ float Bs[16][128];
    int z = blockIdx.z;
    A  += (size_t)z * sA;  Bm += (size_t)z * sB;  Cm += (size_t)z * sC;
    int tid = threadIdx.x;
    int tx = tid & 15, ty = tid >> 4;
    int row0 = blockIdx.y * 128, col0 = blockIdx.x * 128;
    int ar = tid >> 2, ac = (tid & 3) * 4;         // A: rows ar, ar+64 ; 4 k each
    int br = tid >> 5, bc = (tid & 31) * 4;        // B(NN): rows br, br+8 ; 4 n each
    int bn = tid >> 1, bk = (tid & 1) * 8;         // B(NT): row bn ; 8 k each

    float acc[8][8];
    #pragma unroll
    for (int i = 0; i < 8; i++)
        #pragma unroll
        for (int j = 0; j < 8; j++) acc[i][j] = 0.f;

    for (int k0 = 0; k0 < K; k0 += 16) {
        #pragma unroll
        for (int p = 0; p < 2; p++) {
            int r = ar + p * 64;
            float4 va = *(const float4*)(A + (size_t)(row0 + r) * K + k0 + ac);
            As[ac + 0][r] = va.x; As[ac + 1][r] = va.y;
            As[ac + 2][r] = va.z; As[ac + 3][r] = va.w;
        }
        if (!TRANSB) {
            #pragma unroll
            for (int p = 0; p < 2; p++) {
                int r = br + p * 8;
                float4 vb = *(const float4*)(Bm + (size_t)(k0 + r) * N + col0 + bc);
                *(float4*)&Bs[r][bc] = vb;
            }
        } else {
            #pragma unroll
            for (int p = 0; p < 2; p++) {
                float4 vb = *(const float4*)(Bm + (size_t)(col0 + bn) * K + k0 + bk + p * 4);
                Bs[bk + p * 4 + 0][bn] = vb.x; Bs[bk + p * 4 + 1][bn] = vb.y;
                Bs[bk + p * 4 + 2][bn] = vb.z; Bs[bk + p * 4 + 3][bn] = vb.w;
            }
        }
        __syncthreads();
        #pragma unroll
        for (int kk = 0; kk < 16; kk++) {
            float a[8], b[8];
            *(float4*)(a)     = *(const float4*)&As[kk][ty * 8];
            *(float4*)(a + 4) = *(const float4*)&As[kk][ty * 8 + 4];
            *(float4*)(b)     = *(const float4*)&Bs[kk][tx * 8];
            *(float4*)(b + 4) = *(const float4*)&Bs[kk][tx * 8 + 4];
            #pragma unroll
            for (int i = 0; i < 8; i++)
                #pragma unroll
                for (int j = 0; j < 8; j++) acc[i][j] += a[i] * b[j];
        }
        __syncthreads();
    }
    #pragma unroll
    for (int i = 0; i < 8; i++) {
        int r = row0 + ty * 8 + i;
        float rb = (BIAS_MODE == 1) ? bias[r] : 0.f;
        #pragma unroll
        for (int j = 0; j < 8; j += 4) {
            int cidx = col0 + tx * 8 + j;
            float4 o;
            o.x = acc[i][j + 0] + (BIAS_MODE == 2 ? bias[cidx + 0] : rb);
            o.y = acc[i][j + 1] + (BIAS_MODE == 2 ? bias[cidx + 1] : rb);
            o.z = acc[i][j + 2] + (BIAS_MODE == 2 ? bias[cidx + 2] : rb);
            o.w = acc[i][j + 3] + (BIAS_MODE == 2 ? bias[cidx + 3] : rb);
            if (RELU) {
                o.x = fmaxf(o.x, 0.f); o.y = fmaxf(o.y, 0.f);
                o.z = fmaxf(o.z, 0.f); o.w = fmaxf(o.w, 0.f);
            }
            *(float4*)(Cm + (size_t)r * N + cidx) = o;
        }
    }
}

// ---------------- conv2 (3x3, C->C) as implicit-im2col GEMM, + identity + ReLU ----------------
__global__ void __launch_bounds__(256) conv2_gemm(const float* __restrict__ W2,
                                                  const float* __restrict__ hp,
                                                  const float* __restrict__ x,
                                                  const float* __restrict__ c2b,
                                                  const float* __restrict__ idw,
                                                  const float* __restrict__ idb,
                                                  float* __restrict__ down) {
    __shared__ float As[16][128];
    __shared__ float Bs[16][128];
    int z = blockIdx.z;
    const float* hpb = hp + (size_t)z * C_ * PW * PW;
    const float* xb  = x + z * HW * HW;
    int tid = threadIdx.x;
    int tx = tid & 15, ty = tid >> 4;
    int row0 = blockIdx.y * 128, col0 = blockIdx.x * 128;
    int ar = tid >> 2, ac = (tid & 3) * 4;
    int bkk = tid >> 4;                 // k-row within tile 0..15
    int bnn = (tid & 15) * 8;           // 8 consecutive n per thread

    float acc[8][8];
    #pragma unroll
    for (int i = 0; i < 8; i++)
        #pragma unroll
        for (int j = 0; j < 8; j++) acc[i][j] = 0.f;

    for (int k0 = 0; k0 < K2; k0 += 16) {
        #pragma unroll
        for (int p = 0; p < 2; p++) {
            int r = ar + p * 64;
            float4 va = *(const float4*)(W2 + (size_t)(row0 + r) * K2 + k0 + ac);
            As[ac + 0][r] = va.x; As[ac + 1][r] = va.y;
            As[ac + 2][r] = va.z; As[ac + 3][r] = va.w;
        }
        {
            int k = k0 + bkk;
            int ic = k / 9;
            int t  = k - ic * 9;
            int ky = t / 3;
            int kx = t - ky * 3;
            const float* src = hpb + (size_t)ic * (PW * PW) + ky * PW + kx;
            #pragma unroll
            for (int j = 0; j < 8; j++) {
                int n  = col0 + bnn + j;
                int y  = n / HW;
                int xp = n - y * HW;
                Bs[bkk][bnn + j] = src[y * PW + xp];
            }
        }
        __syncthreads();
        #pragma unroll
        for (int kk = 0; kk < 16; kk++) {
            float a[8], b[8];
            *(float4*)(a)     = *(const float4*)&As[kk][ty * 8];
            *(float4*)(a + 4) = *(const float4*)&As[kk][ty * 8 + 4];
            *(float4*)(b)     = *(const float4*)&Bs[kk][tx * 8];
            *(float4*)(b + 4) = *(const float4*)&Bs[kk][tx * 8 + 4];
            #pragma unroll
            for (int i = 0; i < 8; i++)
                #pragma unroll
                for (int j = 0; j < 8; j++) acc[i][j] += a[i] * b[j];
        }
        __syncthreads();
    }
    float* db = down + (size_t)z * C_ * N_;
    #pragma unroll
    for (int i = 0; i < 8; i++) {
        int r = row0 + ty * 8 + i;
        float cb = c2b[r] + idb[r];
        float iw = idw[r];
        #pragma unroll
        for (int j = 0; j < 8; j += 4) {
            int cidx = col0 + tx * 8 + j;
            float4 o;
            o.x = fmaxf(acc[i][j + 0] + cb + iw * xb[cidx + 0], 0.f);
            o.y = fmaxf(acc[i][j + 1] + cb + iw * xb[cidx + 1], 0.f);
            o.z = fmaxf(acc[i][j + 2] + cb + iw * xb[cidx + 2], 0.f);
            o.w = fmaxf(acc[i][j + 3] + cb + iw * xb[cidx + 3], 0.f);
            *(float4*)(db + (size_t)r * N_ + cidx) = o;
        }
    }
}

// ---------------- softmax with rel-pos bias (computed analytically) ----------------
__global__ void softmax_bias(float* __restrict__ qk, const float* __restrict__ rel) {
    __shared__ float red[256];
    int row = blockIdx.x;                 // 0..B*E-1
    int b = row / E_;
    int i = row - b * E_;
    int ci = i / HW, wi = i - ci * HW;
    float* rp = qk + (size_t)row * E_;
    int tid = threadIdx.x;
    float v[9];
    float mx = -3.4e38f;
    #pragma unroll
    for (int r = 0; r < 9; r++) {
        int j = r * 256 + tid;
        int cj = j / HW, wj = j - cj * HW;
        int idx = (ci - cj + HW - 1) * (2 * HW - 1) + (wi - wj + HW - 1);
        v[r] = rp[j] * (1.0f / 48.0f) + rel[idx * NH_ + b];
        mx = fmaxf(mx, v[r]);
    }
    mx = block_max(mx, red);
    float s = 0.f;
    #pragma unroll
    for (int r = 0; r < 9; r++) { v[r] = __expf(v[r] - mx); s += v[r]; }
    s = block_sum(s, red);
    float inv = 1.f / s;
    #pragma unroll
    for (int r = 0; r < 9; r++) rp[r * 256 + tid] = v[r] * inv;
}

// ---------------- permute(1,0,2)-shuffle + residual + LayerNorm (ln1) ----------------
__global__ void add_shuffle_ln(const float* __restrict__ ao, const float* __restrict__ down,
                               const float* __restrict__ g, const float* __restrict__ be,
                               float* __restrict__ h1) {
    __shared__ float red[256];
    int m = blockIdx.x;                    // m = b'*2304 + c'
    int e = m >> 2, bs = m & 3;            // source (b, e) in ao
    const float* ar = ao + ((size_t)bs * E_ + e) * N_;
    const float* dr = down + (size_t)m * N_;
    int tid = threadIdx.x;
    float v[9]; float s = 0.f;
    #pragma unroll
    for (int r = 0; r < 9; r++) { int j = r * 256 + tid; v[r] = ar[j] + dr[j]; s += v[r]; }
    float mean = block_sum(s, red) * (1.f / N_);
    float s2 = 0.f;
    #pragma unroll
    for (int r = 0; r < 9; r++) { float d = v[r] - mean; s2 += d * d; }
    float var = block_sum(s2, red) * (1.f / N_);
    float rstd = rsqrtf(var + 1e-5f);
    #pragma unroll
    for (int r = 0; r < 9; r++) {
        int j = r * 256 + tid;
        h1[(size_t)m * N_ + j] = (v[r] - mean) * rstd * g[j] + be[j];
    }
}

// ---------------- residual + LayerNorm (ln2) -> writes final 'out' ----------------
__global__ void add_ln(const float* __restrict__ f, const float* __restrict__ h1,
                       const float* __restrict__ g, const float* __restrict__ be,
                       float* __restrict__ out) {
    __shared__ float red[256];
    int m = blockIdx.x;
    const float* fr = f + (size_t)m * N_;
    const float* hr = h1 + (size_t)m * N_;
    int tid = threadIdx.x;
    float v[9]; float s = 0.f;
    #pragma unroll
    for (int r = 0; r < 9; r++) { int j = r * 256 + tid; v[r] = fr[j] + hr[j]; s += v[r]; }
    float mean = block_sum(s, red) * (1.f / N_);
    float s2 = 0.f;
    #pragma unroll
    for (int r = 0; r < 9; r++) { float d = v[r] - mean; s2 += d * d; }
    float var = block_sum(s2, red) * (1.f / N_);
    float rstd = rsqrtf(var + 1e-5f);
    #pragma unroll
    for (int r = 0; r < 9; r++) {
        int j = r * 256 + tid;
        out[(size_t)m * N_ + j] = (v[r] - mean) * rstd * g[j] + be[j];
    }
}

// ---------------- maxpool 2x2 ----------------
__global__ void maxpool_k(const float* __restrict__ out, float* __restrict__ p) {
    int idx = blockIdx.x * 256 + threadIdx.x;   // total 4*2304*24*24 = 20736*256
    int bc = idx / (24 * 24);
    int r  = idx - bc * 576;
    int y  = r / 24, x = r - y * 24;
    const float* o = out + (size_t)bc * N_ + (2 * y) * HW + 2 * x;
    p[idx] = fmaxf(fmaxf(o[0], o[1]), fmaxf(o[HW], o[HW + 1]));
}

// ---------------- launcher ----------------
extern "C" void kernel_launch(void* const* d_in, const int* in_sizes, int n_in,
                              void* d_out, int out_size) {
    const float* x    = (const float*)d_in[0];
    const float* c1w  = (const float*)d_in[1];
    const float* c1b  = (const float*)d_in[2];
    const float* c2w  = (const float*)d_in[3];
    const float* c2b  = (const float*)d_in[4];
    const float* idw  = (const float*)d_in[5];
    const float* idb  = (const float*)d_in[6];
    const float* qw   = (const float*)d_in[7];
    const float* qb   = (const float*)d_in[8];
    const float* kw   = (const float*)d_in[9];
    const float* kb   = (const float*)d_in[10];
    const float* vw   = (const float*)d_in[11];
    const float* vb   = (const float*)d_in[12];
    const float* rel  = (const float*)d_in[13];
    const float* ln1g = (const float*)d_in[14];
    const float* ln1b = (const float*)d_in[15];
    const float* ln2g = (const float*)d_in[16];
    const float* ln2b = (const float*)d_in[17];
    const float* fw1  = (const float*)d_in[18];
    const float* fb1  = (const float*)d_in[19];
    const float* fw2  = (const float*)d_in[20];
    const float* fb2  = (const float*)d_in[21];

    float* outp = (float*)d_out;
    float* pool = outp + (size_t)B_ * C_ * N_;

    float *hp, *down, *q, *k, *v, *qk, *ao, *h1, *mid, *f;
    cudaGetSymbolAddress((void**)&hp,   g_hp);
    cudaGetSymbolAddress((void**)&down, g_down);
    cudaGetSymbolAddress((void**)&q,    g_q);
    cudaGetSymbolAddress((void**)&k,    g_k);
    cudaGetSymbolAddress((void**)&v,    g_v);
    cudaGetSymbolAddress((void**)&qk,   g_qk);
    cudaGetSymbolAddress((void**)&ao,   g_ao);
    cudaGetSymbolAddress((void**)&h1,   g_h1);
    cudaGetSymbolAddress((void**)&mid,  g_mid);
    cudaGetSymbolAddress((void**)&f,    g_f);

    const long long EN = (long long)E_ * N_;

    // Stage 1: conv1 + relu, stored zero-padded
    conv1_relu_pad<<<90000, 256>>>(x, c1w, c1b, hp);
    // Stage 2: conv2 (implicit GEMM) + identity conv + relu -> down
    conv2_gemm<<<dim3(18, 18, 4), 256>>>(c2w, hp, x, c2b, idw, idb, down);
    // Stage 3: q/k/v 1x1 convs (GEMMs, weight shared across batch, per-row bias)
    sgemm<1, false, false><<<dim3(18, 18, 4), 256>>>(qw, down, q, qb, E_, N_, C_, 0, EN, EN);
    sgemm<1, false, false><<<dim3(18, 18, 4), 256>>>(kw, down, k, kb, E_, N_, C_, 0, EN, EN);
    sgemm<1, false, false><<<dim3(18, 18, 4), 256>>>(vw, down, v, vb, E_, N_, C_, 0, EN, EN);
    // Stage 4: qk = q @ k^T (NT GEMM, raw; scale+bias folded into softmax)
    sgemm<0, false, true><<<dim3(18, 18, 4), 256>>>(q, k, qk, nullptr, E_, E_, N_, EN, EN, EN);
    // Stage 5: softmax(qk/48 + relpos_bias), in place
    softmax_bias<<<B_ * E_, 256>>>(qk, rel);
    // Stage 6: ao = attn @ v
    sgemm<0, false, false><<<dim3(18, 18, 4), 256>>>(qk, v, ao, nullptr, E_, N_, E_, EN, EN, EN);
    // Stage 7: permute-shuffle + residual + LN1
    add_shuffle_ln<<<B_ * C_, 256>>>(ao, down, ln1g, ln1b, h1);
    // Stage 8: FFN
    sgemm<2, true,  false><<<dim3(36, 72, 1), 256>>>(h1,  fw1, mid, fb1, B_ * N_, E2, E_, 0, 0, 0);
    sgemm<2, false, false><<<dim3(18, 72, 1), 256>>>(mid, fw2, f,   fb2, B_ * N_, E_, E2, 0, 0, 0);
    // Stage 9: residual + LN2 -> out
    add_ln<<<B_ * C_, 256>>>(f, h1, ln2g, ln2b, outp);
    // Stage 10: maxpool 2x2 -> p
    maxpool_k<<<20736, 256>>>(outp, pool);
}

// round 3
// speedup vs baseline: 1.0300x; 1.0300x over previous
#include <cuda_runtime.h>

// ---------------- problem constants ----------------
#define B_  4
#define C_  2304
#define N_  2304          // H*W
#define E_  2304
#define HW  48
#define PW  50            // padded width (48 + 2)
#define NH_ 4
#define K2  20736         // C_*9, conv2 GEMM K
#define E2  4608          // 2*E

// ---------------- device scratch (static, allowed) ----------------
__device__ float g_hp  [(size_t)B_ * C_ * PW * PW];   // padded relu(conv1) : 92 MB
__device__ float g_down[(size_t)B_ * C_ * N_];
__device__ float g_q   [(size_t)B_ * C_ * N_];
__device__ float g_k   [(size_t)B_ * C_ * N_];
__device__ float g_v   [(size_t)B_ * C_ * N_];
__device__ float g_qk  [(size_t)B_ * C_ * N_];        // also attn (in place)
__device__ float g_ao  [(size_t)B_ * C_ * N_];
__device__ float g_h1  [(size_t)B_ * C_ * N_];
__device__ float g_mid [(size_t)B_ * N_ * E2];        // FFN hidden : 170 MB
__device__ float g_f   [(size_t)B_ * C_ * N_];

// ---------------- block reductions ----------------
__device__ __forceinline__ float block_sum(float v, float* red) {
    int tid = threadIdx.x;
    red[tid] = v; __syncthreads();
    #pragma unroll
    for (int s = 128; s > 0; s >>= 1) {
        if (tid < s) red[tid] += red[tid + s];
        __syncthreads();
    }
    float r = red[0]; __syncthreads();
    return r;
}
__device__ __forceinline__ float block_max(float v, float* red) {
    int tid = threadIdx.x;
    red[tid] = v; __syncthreads();
    #pragma unroll
    for (int s = 128; s > 0; s >>= 1) {
        if (tid < s) red[tid] = fmaxf(red[tid], red[tid + s]);
        __syncthreads();
    }
    float r = red[0]; __syncthreads();
    return r;
}

// ---------------- conv1 (3x3, 1->C) + ReLU, written zero-padded ----------------
__global__ void conv1_relu_pad(const float* __restrict__ x, const float* __restrict__ w,
                               const float* __restrict__ bia, float* __restrict__ hp) {
    int idx = blockIdx.x * 256 + threadIdx.x;            // total = 4*2304*2500 = 90000*256
    int b   = idx / (C_ * PW * PW);
    int rem = idx - b * (C_ * PW * PW);
    int c   = rem / (PW * PW);
    int p   = rem - c * (PW * PW);
    int yy  = p / PW, xx = p - yy * PW;
    float out = 0.f;
    if (yy >= 1 && yy <= HW && xx >= 1 && xx <= HW) {
        int y = yy - 1, x0 = xx - 1;
        float acc = bia[c];
        const float* xb = x + b * HW * HW;
        #pragma unroll
        for (int ky = 0; ky < 3; ky++) {
            int iy = y + ky - 1;
            if (iy < 0 || iy >= HW) continue;
            #pragma unroll
            for (int kx = 0; kx < 3; kx++) {
                int ix = x0 + kx - 1;
                if (ix < 0 || ix >= HW) continue;
                acc += w[c * 9 + ky * 3 + kx] * xb[iy * HW + ix];
            }
        }
        out = fmaxf(acc, 0.f);
    }
    hp[idx] = out;
}

// ---------------- generic 128x128x16 SGEMM ----------------
// BIAS_MODE: 0 none, 1 per-row (bias[m]), 2 per-col (bias[n]). TRANSB: B stored (N,K) row-major.
template<int BIAS_MODE, bool RELU, bool TRANSB>
__global__ void __launch_bounds__(256) sgemm(const float* __restrict__ A,
                                             const float* __restrict__ Bm,
                                             float* __restrict__ Cm,
                                             const float* __restrict__ bias,
                                             int M, int N, int K,
                                             long long sA, long long sB, long long sC) {
    __shared__ float As[16][128];
    __shared__ float Bs[16][128];
    int z = blockIdx.z;
    A  += (size_t)z * sA;  Bm += (size_t)z * sB;  Cm += (size_t)z * sC;
    int tid = threadIdx.x;
    int tx = tid & 15, ty = tid >> 4;
    int row0 = blockIdx.y * 128, col0 = blockIdx.x * 128;
    int ar = tid >> 2, ac = (tid & 3) * 4;         // A: rows ar, ar+64 ; 4 k each
    int br = tid >> 5, bc = (tid & 31) * 4;        // B(NN): rows br, br+8 ; 4 n each
    int bn = tid >> 1, bk = (tid & 1) * 8;         // B(NT): row bn ; 8 k each

    float acc[8][8];
    #pragma unroll
    for (int i = 0; i < 8; i++)
        #pragma unroll
        for (int j = 0; j < 8; j++) acc[i][j] = 0.f;

    for (int k0 = 0; k0 < K; k0 += 16) {
        #pragma unroll
        for (int p = 0; p < 2; p++) {
            int r = ar + p * 64;
            float4 va = *(const float4*)(A + (size_t)(row0 + r) * K + k0 + ac);
            As[ac + 0][r] = va.x; As[ac + 1][r] = va.y;
            As[ac + 2][r] = va.z; As[ac + 3][r] = va.w;
        }
        if (!TRANSB) {
            #pragma unroll
            for (int p = 0; p < 2; p++) {
                int r = br + p * 8;
                float4 vb = *(const float4*)(Bm + (size_t)(k0 + r) * N + col0 + bc);
                *(float4*)&Bs[r][bc] = vb;
            }
        } else {
            #pragma unroll
            for (int p = 0; p < 2; p++) {
                float4 vb = *(const float4*)(Bm + (size_t)(col0 + bn) * K + k0 + bk + p * 4);
                Bs[bk + p * 4 + 0][bn] = vb.x; Bs[bk + p * 4 + 1][bn] = vb.y;
                Bs[bk + p * 4 + 2][bn] = vb.z; Bs[bk + p * 4 + 3][bn] = vb.w;
            }
        }
        __syncthreads();
        #pragma unroll
        for (int kk = 0; kk < 16; kk++) {
            float a[8], b[8];
            *(float4*)(a)     = *(const float4*)&As[kk][ty * 8];
            *(float4*)(a + 4) = *(const float4*)&As[kk][ty * 8 + 4];
            *(float4*)(b)     = *(const float4*)&Bs[kk][tx * 8];
            *(float4*)(b + 4) = *(const float4*)&Bs[kk][tx * 8 + 4];
            #pragma unroll
            for (int i = 0; i < 8; i++)
                #pragma unroll
                for (int j = 0; j < 8; j++) acc[i][j] += a[i] * b[j];
        }
        __syncthreads();
    }
    #pragma unroll
    for (int i = 0; i < 8; i++) {
        int r = row0 + ty * 8 + i;
        float rb = (BIAS_MODE == 1) ? bias[r] : 0.f;
        #pragma unroll
        for (int j = 0; j < 8; j += 4) {
            int cidx = col0 + tx * 8 + j;
            float4 o;
            o.x = acc[i][j + 0] + (BIAS_MODE == 2 ? bias[cidx + 0] : rb);
            o.y = acc[i][j + 1] + (BIAS_MODE == 2 ? bias[cidx + 1] : rb);
            o.z = acc[i][j + 2] + (BIAS_MODE == 2 ? bias[cidx + 2] : rb);
            o.w = acc[i][j + 3] + (BIAS_MODE == 2 ? bias[cidx + 3] : rb);
            if (RELU) {
                o.x = fmaxf(o.x, 0.f); o.y = fmaxf(o.y, 0.f);
                o.z = fmaxf(o.z, 0.f); o.w = fmaxf(o.w, 0.f);
            }
            *(float4*)(Cm + (size_t)r * N + cidx) = o;
        }
    }
}

// ---------------- conv2 (3x3, C->C) as implicit-im2col GEMM, + identity + ReLU ----------------
__global__ void __launch_bounds__(256) conv2_gemm(const float* __restrict__ W2,
                                                  const float* __restrict__ hp,
                                                  const float* __restrict__ x,
                                                  const float* __restrict__ c2b,
                                                  const float* __restrict__ idw,
                                                  const float* __restrict__ idb,
                                                  float* __restrict__ down) {
    __shared__ float As[16][128];
    __shared__ float Bs[16][128];
    int z = blockIdx.z;
    const float* hpb = hp + (size_t)z * C_ * PW * PW;
    const float* xb  = x + z * HW * HW;
    int tid = threadIdx.x;
    int tx = tid & 15, ty = tid >> 4;
    int row0 = blockIdx.y * 128, col0 = blockIdx.x * 128;
    int ar = tid >> 2, ac = (tid & 3) * 4;
    int bkk = tid >> 4;                 // k-row within tile 0..15
    int bnn = (tid & 15) * 8;           // 8 consecutive n per thread

    float acc[8][8];
    #pragma unroll
    for (int i = 0; i < 8; i++)
        #pragma unroll
        for (int j = 0; j < 8; j++) acc[i][j] = 0.f;

    for (int k0 = 0; k0 < K2; k0 += 16) {
        #pragma unroll
        for (int p = 0; p < 2; p++) {
            int r = ar + p * 64;
            float4 va = *(const float4*)(W2 + (size_t)(row0 + r) * K2 + k0 + ac);
            As[ac + 0][r] = va.x; As[ac + 1][r] = va.y;
            As[ac + 2][r] = va.z; As[ac + 3][r] = va.w;
        }
        {
            int k = k0 + bkk;
            int ic = k / 9;
            int t  = k - ic * 9;
            int ky = t / 3;
            int kx = t - ky * 3;
            const float* src = hpb + (size_t)ic * (PW * PW) + ky * PW + kx;
            #pragma unroll
            for (int j = 0; j < 8; j++) {
                int n  = col0 + bnn + j;
                int y  = n / HW;
                int xp = n - y * HW;
                Bs[bkk][bnn + j] = src[y * PW + xp];
            }
        }
        __syncthreads();
        #pragma unroll
        for (int kk = 0; kk < 16; kk++) {
            float a[8], b[8];
            *(float4*)(a)     = *(const float4*)&As[kk][ty * 8];
            *(float4*)(a + 4) = *(const float4*)&As[kk][ty * 8 + 4];
            *(float4*)(b)     = *(const float4*)&Bs[kk][tx * 8];
            *(float4*)(b + 4) = *(const float4*)&Bs[kk][tx * 8 + 4];
            #pragma unroll
            for (int i = 0; i < 8; i++)
                #pragma unroll
                for (int j = 0; j < 8; j++) acc[i][j] += a[i] * b[j];
        }
        __syncthreads();
    }
    float* db = down + (size_t)z * C_ * N_;
    #pragma unroll
    for (int i = 0; i < 8; i++) {
        int r = row0 + ty * 8 + i;
        float cb = c2b[r] + idb[r];
        float iw = idw[r];
        #pragma unroll
        for (int j = 0; j < 8; j += 4) {
            int cidx = col0 + tx * 8 + j;
            float4 o;
            o.x = fmaxf(acc[i][j + 0] + cb + iw * xb[cidx + 0], 0.f);
            o.y = fmaxf(acc[i][j + 1] + cb + iw * xb[cidx + 1], 0.f);
            o.z = fmaxf(acc[i][j + 2] + cb + iw * xb[cidx + 2], 0.f);
            o.w = fmaxf(acc[i][j + 3] + cb + iw * xb[cidx + 3], 0.f);
            *(float4*)(db + (size_t)r * N_ + cidx) = o;
        }
    }
}

// ---------------- softmax with rel-pos bias (computed analytically) ----------------
__global__ void softmax_bias(float* __restrict__ qk, const float* __restrict__ rel) {
    __shared__ float red[256];
    int row = blockIdx.x;                 // 0..B*E-1
    int b = row / E_;
    int i = row - b * E_;
    int ci = i / HW, wi = i - ci * HW;
    float* rp = qk + (size_t)row * E_;
    int tid = threadIdx.x;
    float v[9];
    float mx = -3.4e38f;
    #pragma unroll
    for (int r = 0; r < 9; r++) {
        int j = r * 256 + tid;
        int cj = j / HW, wj = j - cj * HW;
        int idx = (ci - cj + HW - 1) * (2 * HW - 1) + (wi - wj + HW - 1);
        v[r] = rp[j] * (1.0f / 48.0f) + rel[idx * NH_ + b];
        mx = fmaxf(mx, v[r]);
    }
    mx = block_max(mx, red);
    float s = 0.f;
    #pragma unroll
    for (int r = 0; r < 9; r++) { v[r] = __expf(v[r] - mx); s += v[r]; }
    s = block_sum(s, red);
    float inv = 1.f / s;
    #pragma unroll
    for (int r = 0; r < 9; r++) rp[r * 256 + tid] = v[r] * inv;
}

// ---------------- permute(1,0,2)-shuffle + residual + LayerNorm (ln1) ----------------
__global__ void add_shuffle_ln(const float* __restrict__ ao, const float* __restrict__ down,
                               const float* __restrict__ g, const float* __restrict__ be,
                               float* __restrict__ h1) {
    __shared__ float red[256];
    int m = blockIdx.x;                    // m = b'*2304 + c'
    int e = m >> 2, bs = m & 3;            // source (b, e) in ao
    const float* ar = ao + ((size_t)bs * E_ + e) * N_;
    const float* dr = down + (size_t)m * N_;
    int tid = threadIdx.x;
    float v[9]; float s = 0.f;
    #pragma unroll
    for (int r = 0; r < 9; r++) { int j = r * 256 + tid; v[r] = ar[j] + dr[j]; s += v[r]; }
    float mean = block_sum(s, red) * (1.f / N_);
    float s2 = 0.f;
    #pragma unroll
    for (int r = 0; r < 9; r++) { float d = v[r] - mean; s2 += d * d; }
    float var = block_sum(s2, red) * (1.f / N_);
    float rstd = rsqrtf(var + 1e-5f);
    #pragma unroll
    for (int r = 0; r < 9; r++) {
        int j = r * 256 + tid;
        h1[(size_t)m * N_ + j] = (v[r] - mean) * rstd * g[j] + be[j];
    }
}

// ---------------- residual + LayerNorm (ln2) -> writes final 'out' ----------------
__global__ void add_ln(const float* __restrict__ f, const float* __restrict__ h1,
                       const float* __restrict__ g, const float* __restrict__ be,
                       float* __restrict__ out) {
    __shared__ float red[256];
    int m = blockIdx.x;
    const float* fr = f + (size_t)m * N_;
    const float* hr = h1 + (size_t)m * N_;
    int tid = threadIdx.x;
    float v[9]; float s = 0.f;
    #pragma unroll
    for (int r = 0; r < 9; r++) { int j = r * 256 + tid; v[r] = fr[j] + hr[j]; s += v[r]; }
    float mean = block_sum(s, red) * (1.f / N_);
    float s2 = 0.f;
    #pragma unroll
    for (int r = 0; r < 9; r++) { float d = v[r] - mean; s2 += d * d; }
    float var = block_sum(s2, red) * (1.f / N_);
    float rstd = rsqrtf(var + 1e-5f);
    #pragma unroll
    for (int r = 0; r < 9; r++) {
        int j = r * 256 + tid;
        out[(size_t)m * N_ + j] = (v[r] - mean) * rstd * g[j] + be[j];
    }
}

// ---------------- maxpool 2x2 ----------------
__global__ void maxpool_k(const float* __restrict__ out, float* __restrict__ p) {
    int idx = blockIdx.x * 256 + threadIdx.x;   // total 4*2304*24*24 = 20736*256
    int bc = idx / (24 * 24);
    int r  = idx - bc * 576;
    int y  = r / 24, x = r - y * 24;
    const float* o = out + (size_t)bc * N_ + (2 * y) * HW + 2 * x;
    p[idx] = fmaxf(fmaxf(o[0], o[1]), fmaxf(o[HW], o[HW + 1]));
}

// ---------------- launcher ----------------
extern "C" void kernel_launch(void* const* d_in, const int* in_sizes, int n_in,
                              void* d_out, int out_size) {
    const float* x    = (const float*)d_in[0];
    const float* c1w  = (const float*)d_in[1];
    const float* c1b  = (const float*)d_in[2];
    const float* c2w  = (const float*)d_in[3];
    const float* c2b  = (const float*)d_in[4];
    const float* idw  = (const float*)d_in[5];
    const float* idb  = (const float*)d_in[6];
    const float* qw   = (const float*)d_in[7];
    const float* qb   = (const float*)d_in[8];
    const float* kw   = (const float*)d_in[9];
    const float* kb   = (const float*)d_in[10];
    const float* vw   = (const float*)d_in[11];
    const float* vb   = (const float*)d_in[12];
    const float* rel  = (const float*)d_in[13];
    const float* ln1g = (const float*)d_in[14];
    const float* ln1b = (const float*)d_in[15];
    const float* ln2g = (const float*)d_in[16];
    const float* ln2b = (const float*)d_in[17];
    const float* fw1  = (const float*)d_in[18];
    const float* fb1  = (const float*)d_in[19];
    const float* fw2  = (const float*)d_in[20];
    const float* fb2  = (const float*)d_in[21];

    float* outp = (float*)d_out;
    float* pool = outp + (size_t)B_ * C_ * N_;

    float *hp, *down, *q, *k, *v, *qk, *ao, *h1, *mid, *f;
    cudaGetSymbolAddress((void**)&hp,   g_hp);
    cudaGetSymbolAddress((void**)&down, g_down);
    cudaGetSymbolAddress((void**)&q,    g_q);
    cudaGetSymbolAddress((void**)&k,    g_k);
    cudaGetSymbolAddress((void**)&v,    g_v);
    cudaGetSymbolAddress((void**)&qk,   g_qk);
    cudaGetSymbolAddress((void**)&ao,   g_ao);
    cudaGetSymbolAddress((void**)&h1,   g_h1);
    cudaGetSymbolAddress((void**)&mid,  g_mid);
    cudaGetSymbolAddress((void**)&f,    g_f);

    const long long EN = (long long)E_ * N_;

    // Stage 1: conv1 + relu, stored zero-padded
    conv1_relu_pad<<<90000, 256>>>(x, c1w, c1b, hp);
    // Stage 2: conv2 (implicit GEMM) + identity conv + relu -> down
    conv2_gemm<<<dim3(18, 18, 4), 256>>>(c2w, hp, x, c2b, idw, idb, down);
    // Stage 3: q/k/v 1x1 convs (GEMMs, weight shared across batch, per-row bias)
    sgemm<1, false, false><<<dim3(18, 18, 4), 256>>>(qw, down, q, qb, E_, N_, C_, 0, EN, EN);
    sgemm<1, false, false><<<dim3(18, 18, 4), 256>>>(kw, down, k, kb, E_, N_, C_, 0, EN, EN);
    sgemm<1, false, false><<<dim3(18, 18, 4), 256>>>(vw, down, v, vb, E_, N_, C_, 0, EN, EN);
    // Stage 4: qk = q @ k^T (NT GEMM, raw; scale+bias folded into softmax)
    sgemm<0, false, true><<<dim3(18, 18, 4), 256>>>(q, k, qk, nullptr, E_, E_, N_, EN, EN, EN);
    // Stage 5: softmax(qk/48 + relpos_bias), in place
    softmax_bias<<<B_ * E_, 256>>>(qk, rel);
    // Stage 6: ao = attn @ v
    sgemm<0, false, false><<<dim3(18, 18, 4), 256>>>(qk, v, ao, nullptr, E_, N_, E_, EN, EN, EN);
    // Stage 7: permute-shuffle + residual + LN1
    add_shuffle_ln<<<B_ * C_, 256>>>(ao, down, ln1g, ln1b, h1);
    // Stage 8: FFN
    sgemm<2, true,  false><<<dim3(36, 72, 1), 256>>>(h1,  fw1, mid, fb1, B_ * N_, E2, E_, 0, 0, 0);
    sgemm<2, false, false><<<dim3(18, 72, 1), 256>>>(mid, fw2, f,   fb2, B_ * N_, E_, E2, 0, 0, 0);
    // Stage 9: residual + LN2 -> out
    add_ln<<<B_ * C_, 256>>>(f, h1, ln2g, ln2b, outp);
    // Stage 10: maxpool 2x2 -> p
    maxpool_k<<<20736, 256>>>(outp, pool);
}

// round 5
// speedup vs baseline: 2.6102x; 2.5342x over previous
#include <cuda_runtime.h>
#include <cuda_bf16.h>
#include <cstdint>

#define B_  4
#define C_  2304
#define N_  2304
#define E_  2304
#define HW  48
#define PW  50
#define NH_ 4
#define K2  20736
#define E2  4608

// GEMM tiling
#define BM 128
#define BN 128
#define BK 32
#define TSTRIDE 40                 // padded row stride in bf16 elems (80 B)
#define TILE_BYTES (BM * TSTRIDE * 2)   // 10240
#define STAGE_BYTES (4 * TILE_BYTES)    // 40960: Ah, Al, Bh, Bl
#define NSTAGE 3
#define DSMEM_REQ (NSTAGE * STAGE_BYTES)

// ---------------- PTX helpers ----------------
__device__ __forceinline__ uint32_t smem_u32(const void* p) {
    uint32_t a;
    asm("{ .reg .u64 t; cvta.to.shared.u64 t, %1; cvt.u32.u64 %0, t; }" : "=r"(a) : "l"(p));
    return a;
}
__device__ __forceinline__ void cp16(uint32_t dst, const void* src) {
    asm volatile("cp.async.cg.shared.global [%0], [%1], 16;" :: "r"(dst), "l"(src));
}
__device__ __forceinline__ void cp_commit() { asm volatile("cp.async.commit_group;"); }
template<int NN>
__device__ __forceinline__ void cp_wait() { asm volatile("cp.async.wait_group %0;" :: "n"(NN)); }

__device__ __forceinline__ void ldm4(uint32_t& r0, uint32_t& r1, uint32_t& r2, uint32_t& r3, uint32_t a) {
    asm volatile("ldmatrix.sync.aligned.m8n8.x4.shared.b16 {%0,%1,%2,%3}, [%4];"
                 : "=r"(r0), "=r"(r1), "=r"(r2), "=r"(r3) : "r"(a));
}
__device__ __forceinline__ void mma16816(float* d, uint32_t a0, uint32_t a1, uint32_t a2, uint32_t a3,
                                         uint32_t b0, uint32_t b1) {
    asm volatile("mma.sync.aligned.m16n8k16.row.col.f32.bf16.bf16.f32 "
                 "{%0,%1,%2,%3}, {%4,%5,%6,%7}, {%8,%9}, {%0,%1,%2,%3};"
                 : "+f"(d[0]), "+f"(d[1]), "+f"(d[2]), "+f"(d[3])
                 : "r"(a0), "r"(a1), "r"(a2), "r"(a3), "r"(b0), "r"(b1));
}

__device__ __forceinline__ void split1(float v, __nv_bfloat16& h, __nv_bfloat16& l) {
    h = __float2bfloat16(v);
    l = __float2bfloat16(v - __bfloat162float(h));
}
__device__ __forceinline__ uint32_t pk2(__nv_bfloat16 a, __nv_bfloat16 b) {
    __nv_bfloat162 t(a, b);
    return *reinterpret_cast<uint32_t*>(&t);
}

// ---------------- scratch arenas ----------------
constexpr size_t SZ_EN = (size_t)B_ * E_ * N_;
constexpr size_t SZ_W  = (size_t)E_ * E_;
constexpr size_t F_HP = 0, F_DOWN = 23040000;
constexpr size_t F_QK = F_DOWN + SZ_EN, F_AO = F_QK + SZ_EN, F_H1 = F_AO + SZ_EN;
constexpr size_t F_FF = F_H1 + SZ_EN, F_MID = F_FF + SZ_EN;
constexpr size_t F_Q = F_MID + 2 * SZ_EN, F_K = F_Q + SZ_EN, F_V = F_K + SZ_EN;
constexpr size_t F_TOT = F_V + SZ_EN;

constexpr size_t H_IMH = 0, H_IML = H_IMH + (size_t)B_ * N_ * K2;
constexpr size_t H_W2H = H_IML + (size_t)B_ * N_ * K2, H_W2L = H_W2H + (size_t)C_ * K2;
constexpr size_t H_QWH = H_W2L + (size_t)C_ * K2, H_QWL = H_QWH + SZ_W;
constexpr size_t H_KWH = H_QWL + SZ_W, H_KWL = H_KWH + SZ_W;
constexpr size_t H_VWH = H_KWL + SZ_W, H_VWL = H_VWH + SZ_W;
constexpr size_t H_W1TH = H_VWL + SZ_W, H_W1TL = H_W1TH + 2 * SZ_W;
constexpr size_t H_W2TH = H_W1TL + 2 * SZ_W, H_W2TL = H_W2TH + 2 * SZ_W;
constexpr size_t H_DTH = H_W2TL + 2 * SZ_W, H_DTL = H_DTH + SZ_EN;
constexpr size_t H_VTH = H_DTL + SZ_EN, H_VTL = H_VTH + SZ_EN;
constexpr size_t H_QH = H_VTL + SZ_EN, H_QL = H_QH + SZ_EN;
constexpr size_t H_KH = H_QL + SZ_EN, H_KL = H_KH + SZ_EN;
constexpr size_t H_ATH = H_KL + SZ_EN, H_ATL = H_ATH + SZ_EN;
constexpr size_t H_H1H = H_ATL + SZ_EN, H_H1L = H_H1H + SZ_EN;
constexpr size_t H_MIDH = H_H1L + SZ_EN, H_MIDL = H_MIDH + 2 * SZ_EN;
constexpr size_t H_TOT = H_MIDL + 2 * SZ_EN;

__device__ __align__(256) float         g_f32[F_TOT];
__device__ __align__(256) __nv_bfloat16 g_b16[H_TOT];

// ---------------- mma.sync GEMM: D[m][n] = sum_k A[m,k]*B[n,k] (3xbf16 split) ----------------
// EPI: 0 none, 1 +b1[row], 2 +b1[col]+relu, 3 +b1[col], 4 conv(+b1[r]+b2[r]+b3[r]*b4[z*N_+n], relu)
template<int EPI>
__global__ void __launch_bounds__(256, 1) mm_gemm(
    const __nv_bfloat16* __restrict__ Ah, const __nv_bfloat16* __restrict__ Al,
    const __nv_bfloat16* __restrict__ Bh, const __nv_bfloat16* __restrict__ Bl,
    float* __restrict__ C,
    const float* __restrict__ b1, const float* __restrict__ b2,
    const float* __restrict__ b3, const float* __restrict__ b4,
    int M, int N, int K, int tilesM, int tilesN,
    long long sA, long long sB, long long sC)
{
    extern __shared__ char smem[];
    const uint32_t sb = smem_u32(smem);
    const int tid = threadIdx.x;
    const int wid = tid >> 5, lane = tid & 31;
    const int wm = wid >> 2, wn = wid & 3;          // warp grid 2 (m) x 4 (n)
    const int z = blockIdx.z;

    // GROUP_M=8 raster for L2 reuse
    int bid = blockIdx.x;
    const int GROUP = 8;
    int npg = GROUP * tilesN;
    int grp = bid / npg, rem = bid - grp * npg;
    int gs = tilesM - grp * GROUP; if (gs > GROUP) gs = GROUP;
    int mt = grp * GROUP + rem % gs;
    int nt = rem / gs;
    const int row0 = mt * BM, col0 = nt * BN;

    Ah += (size_t)z * sA; Al += (size_t)z * sA;
    Bh += (size_t)z * sB; Bl += (size_t)z * sB;
    C  += (size_t)z * sC;

    // cp.async mapping: thread t -> row t>>1, two 16B chunks at (t&1)*32 bytes
    const int crow = tid >> 1;
    const int cbyte = (tid & 1) * 32;
    const uint32_t dst_off = (uint32_t)crow * (TSTRIDE * 2) + cbyte;

    auto prefetch = [&](int slab, int st) {
        const int k0 = slab * BK;
        uint32_t base = sb + st * STAGE_BYTES + dst_off;
        const char* srcA_h = (const char*)(Ah + (size_t)(row0 + crow) * K + k0) + cbyte;
        const char* srcA_l = (const char*)(Al + (size_t)(row0 + crow) * K + k0) + cbyte;
        const char* srcB_h = (const char*)(Bh + (size_t)(col0 + crow) * K + k0) + cbyte;
        const char* srcB_l = (const char*)(Bl + (size_t)(col0 + crow) * K + k0) + cbyte;
        cp16(base,                   srcA_h);      cp16(base + 16,                   srcA_h + 16);
        cp16(base + TILE_BYTES,      srcA_l);      cp16(base + TILE_BYTES + 16,      srcA_l + 16);
        cp16(base + 2 * TILE_BYTES,  srcB_h);      cp16(base + 2 * TILE_BYTES + 16,  srcB_h + 16);
        cp16(base + 3 * TILE_BYTES,  srcB_l);      cp16(base + 3 * TILE_BYTES + 16,  srcB_l + 16);
        cp_commit();
    };

    float acc[4][4][4];
    #pragma unroll
    for (int a = 0; a < 4; a++)
        #pragma unroll
        for (int b = 0; b < 4; b++)
            #pragma unroll
            for (int c = 0; c < 4; c++) acc[a][b][c] = 0.f;

    const int S = K / BK;
    prefetch(0, 0);
    prefetch(1, 1);
    cp_wait<1>();
    __syncthreads();

    // ldmatrix lane addressing
    const uint32_t a_row = (uint32_t)(wm * 64 + (lane & 15));     // + mf*16
    const uint32_t a_kh  = (uint32_t)(lane >> 4) * 16;
    const uint32_t b_row = (uint32_t)(wn * 32 + (lane & 7) + ((lane >> 4) & 1) * 8);  // + nf2*16
    const uint32_t b_kh  = (uint32_t)((lane >> 3) & 1) * 16;

    for (int i = 0; i < S; i++) {
        const uint32_t st = sb + (i % NSTAGE) * STAGE_BYTES;
        const uint32_t aH = st + a_row * (TSTRIDE * 2) + a_kh;
        const uint32_t aL = aH + TILE_BYTES;
        const uint32_t bH = st + 2 * TILE_BYTES + b_row * (TSTRIDE * 2) + b_kh;
        const uint32_t bL = bH + TILE_BYTES;

        #pragma unroll
        for (int ks = 0; ks < 2; ks++) {
            const uint32_t ko = ks * 32;
            uint32_t ah[4][4], al[4][4], bh[2][4], bl[2][4];
            #pragma unroll
            for (int mf = 0; mf < 4; mf++) {
                uint32_t adr = aH + ko + (uint32_t)mf * 16 * (TSTRIDE * 2);
                ldm4(ah[mf][0], ah[mf][1], ah[mf][2], ah[mf][3], adr);
                ldm4(al[mf][0], al[mf][1], al[mf][2], al[mf][3], adr + TILE_BYTES);
            }
            #pragma unroll
            for (int p = 0; p < 2; p++) {
                uint32_t adr = bH + ko + (uint32_t)p * 16 * (TSTRIDE * 2);
                ldm4(bh[p][0], bh[p][1], bh[p][2], bh[p][3], adr);
                ldm4(bl[p][0], bl[p][1], bl[p][2], bl[p][3], adr + TILE_BYTES);
            }
            #pragma unroll
            for (int mf = 0; mf < 4; mf++)
                #pragma unroll
                for (int nf = 0; nf < 4; nf++) {
                    uint32_t h0 = bh[nf >> 1][(nf & 1) * 2], h1 = bh[nf >> 1][(nf & 1) * 2 + 1];
                    uint32_t l0 = bl[nf >> 1][(nf & 1) * 2], l1 = bl[nf >> 1][(nf & 1) * 2 + 1];
                    mma16816(acc[mf][nf], ah[mf][0], ah[mf][1], ah[mf][2], ah[mf][3], h0, h1);
                    mma16816(acc[mf][nf], ah[mf][0], ah[mf][1], ah[mf][2], ah[mf][3], l0, l1);
                    mma16816(acc[mf][nf], al[mf][0], al[mf][1], al[mf][2], al[mf][3], h0, h1);
                }
        }
        if (i + 2 < S) prefetch(i + 2, (i + 2) % NSTAGE);
        if (i + 1 < S) cp_wait<1>(); else cp_wait<0>();
        __syncthreads();
    }

    // epilogue
    #pragma unroll
    for (int mf = 0; mf < 4; mf++) {
        #pragma unroll
        for (int h = 0; h < 2; h++) {
            const int r = row0 + wm * 64 + mf * 16 + (lane >> 2) + h * 8;
            float rbias = 0.f, iw = 0.f;
            if (EPI == 1) rbias = b1[r];
            if (EPI == 4) { rbias = b1[r] + b2[r]; iw = b3[r]; }
            float* crow2 = C + (size_t)r * N;
            const float* xrow = (EPI == 4) ? (b4 + (size_t)z * N_) : nullptr;
            #pragma unroll
            for (int nf = 0; nf < 4; nf++) {
                const int cidx = col0 + wn * 32 + nf * 8 + (lane & 3) * 2;
                float2 o;
                o.x = acc[mf][nf][h * 2 + 0];
                o.y = acc[mf][nf][h * 2 + 1];
                if (EPI == 1) { o.x += rbias; o.y += rbias; }
                if (EPI == 2 || EPI == 3) {
                    float2 bc = *(const float2*)(b1 + cidx);
                    o.x += bc.x; o.y += bc.y;
                }
                if (EPI == 4) {
                    float2 xv = *(const float2*)(xrow + cidx);
                    o.x += rbias + iw * xv.x; o.y += rbias + iw * xv.y;
                }
                if (EPI == 2 || EPI == 4) { o.x = fmaxf(o.x, 0.f); o.y = fmaxf(o.y, 0.f); }
                *(float2*)(crow2 + cidx) = o;
            }
        }
    }
}

// ---------------- conv1 (3x3, 1->C) + ReLU, zero-padded ----------------
__global__ void conv1_relu_pad(const float* __restrict__ x, const float* __restrict__ w,
                               const float* __restrict__ bia, float* __restrict__ hp) {
    int idx = blockIdx.x * 256 + threadIdx.x;
    int b = idx / (C_ * PW * PW);
    int rem = idx - b * (C_ * PW * PW);
    int c = rem / (PW * PW);
    int p = rem - c * (PW * PW);
    int yy = p / PW, xx = p - yy * PW;
    float out = 0.f;
    if (yy >= 1 && yy <= HW && xx >= 1 && xx <= HW) {
        int y = yy - 1, x0 = xx - 1;
        float acc = bia[c];
        const float* xb = x + b * HW * HW;
        #pragma unroll
        for (int ky = 0; ky < 3; ky++) {
            int iy = y + ky - 1;
            if (iy < 0 || iy >= HW) continue;
            #pragma unroll
            for (int kx = 0; kx < 3; kx++) {
                int ix = x0 + kx - 1;
                if (ix < 0 || ix >= HW) continue;
                acc += w[c * 9 + ky * 3 + kx] * xb[iy * HW + ix];
            }
        }
        out = fmaxf(acc, 0.f);
    }
    hp[idx] = out;
}

// ---------------- im2col^T + split ----------------
__global__ void im2col_gen(const float* __restrict__ hp,
                           __nv_bfloat16* __restrict__ bh, __nv_bfloat16* __restrict__ bl) {
    __shared__ float s[64][33];
    int t = threadIdx.x;
    int ic0 = blockIdx.x * 64, n0 = blockIdx.y * 32;
    int zo = blockIdx.z, z = zo / 9, off = zo - z * 9;
    int ky = off / 3, kx = off - ky * 3;
    const float* hpz = hp + (size_t)z * C_ * (PW * PW);
    #pragma unroll
    for (int p = 0; p < 2; p++) {
        int icl = p * 32 + (t >> 3);
        int nl = (t & 7) * 4;
        const float* base = hpz + (size_t)(ic0 + icl) * (PW * PW) + ky * PW + kx;
        #pragma unroll
        for (int i = 0; i < 4; i++) {
            int n = n0 + nl + i;
            int y = n / HW, xx = n - y * HW;
            s[icl][nl + i] = base[y * PW + xx];
        }
    }
    __syncthreads();
    int n = t >> 3, icc = (t & 7) * 8;
    size_t o = (size_t)z * ((size_t)N_ * K2) + (size_t)(n0 + n) * K2 + (size_t)off * C_ + ic0 + icc;
    __nv_bfloat16 hh[8], ll[8];
    #pragma unroll
    for (int i = 0; i < 8; i++) split1(s[icc + i][n], hh[i], ll[i]);
    uint4 uh, ul;
    uh.x = pk2(hh[0], hh[1]); uh.y = pk2(hh[2], hh[3]); uh.z = pk2(hh[4], hh[5]); uh.w = pk2(hh[6], hh[7]);
    ul.x = pk2(ll[0], ll[1]); ul.y = pk2(ll[2], ll[3]); ul.z = pk2(ll[4], ll[5]); ul.w = pk2(ll[6], ll[7]);
    *(uint4*)(bh + o) = uh;
    *(uint4*)(bl + o) = ul;
}

// ---------------- W2 reorder+split: out[c][off*C+ic] = W2[c][ic*9+off] ----------------
__global__ void reorder_split_w2(const float* __restrict__ w2,
                                 __nv_bfloat16* __restrict__ oh, __nv_bfloat16* __restrict__ ol) {
    int id = blockIdx.x * 256 + threadIdx.x;
    int c = id / (9 * 288);
    int rem = id - c * (9 * 288);
    int off = rem / 288, icb = rem - off * 288;
    const float* src = w2 + (size_t)c * K2 + (size_t)icb * 72 + off;
    __nv_bfloat16 hh[8], ll[8];
    #pragma unroll
    for (int i = 0; i < 8; i++) split1(src[i * 9], hh[i], ll[i]);
    size_t o = (size_t)c * K2 + (size_t)off * C_ + (size_t)icb * 8;
    uint4 uh, ul;
    uh.x = pk2(hh[0], hh[1]); uh.y = pk2(hh[2], hh[3]); uh.z = pk2(hh[4], hh[5]); uh.w = pk2(hh[6], hh[7]);
    ul.x = pk2(ll[0], ll[1]); ul.y = pk2(ll[2], ll[3]); ul.z = pk2(ll[4], ll[5]); ul.w = pk2(ll[6], ll[7]);
    *(uint4*)(oh + o) = uh;
    *(uint4*)(ol + o) = ul;
}

// ---------------- plain split ----------------
__global__ void split_plain(const float* __restrict__ src,
                            __nv_bfloat16* __restrict__ oh, __nv_bfloat16* __restrict__ ol) {
    size_t i4 = (size_t)blockIdx.x * 256 + threadIdx.x;
    float4 v = *(const float4*)(src + i4 * 4);
    __nv_bfloat16 h0, h1, h2, h3, l0, l1, l2, l3;
    split1(v.x, h0, l0); split1(v.y, h1, l1); split1(v.z, h2, l2); split1(v.w, h3, l3);
    uint2 uh, ul;
    uh.x = pk2(h0, h1); uh.y = pk2(h2, h3);
    ul.x = pk2(l0, l1); ul.y = pk2(l2, l3);
    *(uint2*)(oh + i4 * 4) = uh;
    *(uint2*)(ol + i4 * 4) = ul;
}

// ---------------- transpose + split: in [z][R][Cc] -> out [z][Cc][R] ----------------
__global__ void transpose_split(const float* __restrict__ in,
                                __nv_bfloat16* __restrict__ oh, __nv_bfloat16* __restrict__ ol,
                                int R, int Cc) {
    __shared__ float s[64][33];
    int t = threadIdx.x;
    int c0 = blockIdx.x * 32, r0 = blockIdx.y * 64;
    size_t zb = (size_t)blockIdx.z * R * Cc;
    {
        int r = t >> 2, cl = (t & 3) * 8;
        const float* src = in + zb + (size_t)(r0 + r) * Cc + c0 + cl;
        float4 a = *(const float4*)src;
        float4 b = *(const float4*)(src + 4);
        s[r][cl + 0] = a.x; s[r][cl + 1] = a.y; s[r][cl + 2] = a.z; s[r][cl + 3] = a.w;
        s[r][cl + 4] = b.x; s[r][cl + 5] = b.y; s[r][cl + 6] = b.z; s[r][cl + 7] = b.w;
    }
    __syncthreads();
    int c = t >> 3, rl = (t & 7) * 8;
    __nv_bfloat16 hh[8], ll[8];
    #pragma unroll
    for (int i = 0; i < 8; i++) split1(s[rl + i][c], hh[i], ll[i]);
    size_t o = zb + (size_t)(c0 + c) * R + r0 + rl;
    uint4 uh, ul;
    uh.x = pk2(hh[0], hh[1]); uh.y = pk2(hh[2], hh[3]); uh.z = pk2(hh[4], hh[5]); uh.w = pk2(hh[6], hh[7]);
    ul.x = pk2(ll[0], ll[1]); ul.y = pk2(ll[2], ll[3]); ul.z = pk2(ll[4], ll[5]); ul.w = pk2(ll[6], ll[7]);
    *(uint4*)(oh + o) = uh;
    *(uint4*)(ol + o) = ul;
}

// ---------------- reductions ----------------
__device__ __forceinline__ float block_sum(float v, float* red) {
    int tid = threadIdx.x;
    red[tid] = v; __syncthreads();
    #pragma unroll
    for (int s = 128; s > 0; s >>= 1) { if (tid < s) red[tid] += red[tid + s]; __syncthreads(); }
    float r = red[0]; __syncthreads();
    return r;
}
__device__ __forceinline__ float block_max(float v, float* red) {
    int tid = threadIdx.x;
    red[tid] = v; __syncthreads();
    #pragma unroll
    for (int s = 128; s > 0; s >>= 1) { if (tid < s) red[tid] = fmaxf(red[tid], red[tid + s]); __syncthreads(); }
    float r = red[0]; __syncthreads();
    return r;
}

// ---------------- softmax with analytic rel-pos bias ----------------
__global__ void softmax_bias(float* __restrict__ qk, const float* __restrict__ rel) {
    __shared__ float red[256];
    int row = blockIdx.x;
    int b = row / E_;
    int i = row - b * E_;
    int ci = i / HW, wi = i - ci * HW;
    float* rp = qk + (size_t)row * E_;
    int tid = threadIdx.x;
    float v[9];
    float mx = -3.4e38f;
    #pragma unroll
    for (int r = 0; r < 9; r++) {
        int j = r * 256 + tid;
        int cj = j / HW, wj = j - cj * HW;
        int idx = (ci - cj + HW - 1) * (2 * HW - 1) + (wi - wj + HW - 1);
        v[r] = rp[j] * (1.0f / 48.0f) + rel[idx * NH_ + b];
        mx = fmaxf(mx, v[r]);
    }
    mx = block_max(mx, red);
    float s = 0.f;
    #pragma unroll
    for (int r = 0; r < 9; r++) { v[r] = __expf(v[r] - mx); s += v[r]; }
    s = block_sum(s, red);
    float inv = 1.f / s;
    #pragma unroll
    for (int r = 0; r < 9; r++) rp[r * 256 + tid] = v[r] * inv;
}

// ---------------- shuffle + residual + LN1 ----------------
__global__ void add_shuffle_ln(const float* __restrict__ ao, const float* __restrict__ down,
                               const float* __restrict__ g, const float* __restrict__ be,
                               float* __restrict__ h1) {
    __shared__ float red[256];
    int m = blockIdx.x;
    int e = m >> 2, bs = m & 3;
    const float* ar = ao + ((size_t)bs * E_ + e) * N_;
    const float* dr = down + (size_t)m * N_;
    int tid = threadIdx.x;
    float v[9]; float s = 0.f;
    #pragma unroll
    for (int r = 0; r < 9; r++) { int j = r * 256 + tid; v[r] = ar[j] + dr[j]; s += v[r]; }
    float mean = block_sum(s, red) * (1.f / N_);
    float s2 = 0.f;
    #pragma unroll
    for (int r = 0; r < 9; r++) { float d = v[r] - mean; s2 += d * d; }
    float var = block_sum(s2, red) * (1.f / N_);
    float rstd = rsqrtf(var + 1e-5f);
    #pragma unroll
    for (int r = 0; r < 9; r++) {
        int j = r * 256 + tid;
        h1[(size_t)m * N_ + j] = (v[r] - mean) * rstd * g[j] + be[j];
    }
}

// ---------------- residual + LN2 ----------------
__global__ void add_ln(const float* __restrict__ f, const float* __restrict__ h1,
                       const float* __restrict__ g, const float* __restrict__ be,
                       float* __restrict__ out) {
    __shared__ float red[256];
    int m = blockIdx.x;
    const float* fr = f + (size_t)m * N_;
    const float* hr = h1 + (size_t)m * N_;
    int tid = threadIdx.x;
    float v[9]; float s = 0.f;
    #pragma unroll
    for (int r = 0; r < 9; r++) { int j = r * 256 + tid; v[r] = fr[j] + hr[j]; s += v[r]; }
    float mean = block_sum(s, red) * (1.f / N_);
    float s2 = 0.f;
    #pragma unroll
    for (int r = 0; r < 9; r++) { float d = v[r] - mean; s2 += d * d; }
    float var = block_sum(s2, red) * (1.f / N_);
    float rstd = rsqrtf(var + 1e-5f);
    #pragma unroll
    for (int r = 0; r < 9; r++) {
        int j = r * 256 + tid;
        out[(size_t)m * N_ + j] = (v[r] - mean) * rstd * g[j] + be[j];
    }
}

// ---------------- maxpool 2x2 ----------------
__global__ void maxpool_k(const float* __restrict__ out, float* __restrict__ p) {
    int idx = blockIdx.x * 256 + threadIdx.x;
    int bc = idx / (24 * 24);
    int r = idx - bc * 576;
    int y = r / 24, x = r - y * 24;
    const float* o = out + (size_t)bc * N_ + (2 * y) * HW + 2 * x;
    p[idx] = fmaxf(fmaxf(o[0], o[1]), fmaxf(o[HW], o[HW + 1]));
}

// ---------------- launcher ----------------
extern "C" void kernel_launch(void* const* d_in, const int* in_sizes, int n_in,
                              void* d_out, int out_size) {
    const float* x    = (const float*)d_in[0];
    const float* c1w  = (const float*)d_in[1];
    const float* c1b  = (const float*)d_in[2];
    const float* c2w  = (const float*)d_in[3];
    const float* c2b  = (const float*)d_in[4];
    const float* idw  = (const float*)d_in[5];
    const float* idb  = (const float*)d_in[6];
    const float* qw   = (const float*)d_in[7];
    const float* qb   = (const float*)d_in[8];
    const float* kw   = (const float*)d_in[9];
    const float* kb   = (const float*)d_in[10];
    const float* vw   = (const float*)d_in[11];
    const float* vb   = (const float*)d_in[12];
    const float* rel  = (const float*)d_in[13];
    const float* ln1g = (const float*)d_in[14];
    const float* ln1b = (const float*)d_in[15];
    const float* ln2g = (const float*)d_in[16];
    const float* ln2b = (const float*)d_in[17];
    const float* fw1  = (const float*)d_in[18];
    const float* fb1  = (const float*)d_in[19];
    const float* fw2  = (const float*)d_in[20];
    const float* fb2  = (const float*)d_in[21];

    float* outp = (float*)d_out;
    float* pool = outp + (size_t)B_ * C_ * N_;

    float* F; __nv_bfloat16* Hh;
    cudaGetSymbolAddress((void**)&F, g_f32);
    cudaGetSymbolAddress((void**)&Hh, g_b16);

    float* hp = F + F_HP;   float* down = F + F_DOWN;
    float* q  = F + F_Q;    float* k    = F + F_K;    float* v = F + F_V;
    float* qk = F + F_QK;   float* ao   = F + F_AO;   float* h1 = F + F_H1;
    float* ff = F + F_FF;   float* mid  = F + F_MID;

    cudaFuncSetAttribute(mm_gemm<0>, cudaFuncAttributeMaxDynamicSharedMemorySize, DSMEM_REQ);
    cudaFuncSetAttribute(mm_gemm<1>, cudaFuncAttributeMaxDynamicSharedMemorySize, DSMEM_REQ);
    cudaFuncSetAttribute(mm_gemm<2>, cudaFuncAttributeMaxDynamicSharedMemorySize, DSMEM_REQ);
    cudaFuncSetAttribute(mm_gemm<3>, cudaFuncAttributeMaxDynamicSharedMemorySize, DSMEM_REQ);
    cudaFuncSetAttribute(mm_gemm<4>, cudaFuncAttributeMaxDynamicSharedMemorySize, DSMEM_REQ);

    const long long EN = (long long)E_ * N_;
    const long long NK2 = (long long)N_ * K2;

    // weight prep
    reorder_split_w2<<<23328, 256>>>(c2w, Hh + H_W2H, Hh + H_W2L);
    split_plain<<<5184, 256>>>(qw, Hh + H_QWH, Hh + H_QWL);
    split_plain<<<5184, 256>>>(kw, Hh + H_KWH, Hh + H_KWL);
    split_plain<<<5184, 256>>>(vw, Hh + H_VWH, Hh + H_VWL);
    transpose_split<<<dim3(144, 36, 1), 256>>>(fw1, Hh + H_W1TH, Hh + H_W1TL, E_, E2);
    transpose_split<<<dim3(72, 72, 1), 256>>>(fw2, Hh + H_W2TH, Hh + H_W2TL, E2, E_);

    // conv block
    conv1_relu_pad<<<90000, 256>>>(x, c1w, c1b, hp);
    im2col_gen<<<dim3(36, 72, 36), 256>>>(hp, Hh + H_IMH, Hh + H_IML);
    mm_gemm<4><<<dim3(324, 1, 4), 256, DSMEM_REQ>>>(
        Hh + H_W2H, Hh + H_W2L, Hh + H_IMH, Hh + H_IML, down,
        c2b, idb, idw, x, C_, N_, K2, 18, 18, 0, NK2, EN);

    // qkv
    transpose_split<<<dim3(72, 36, 4), 256>>>(down, Hh + H_DTH, Hh + H_DTL, C_, N_);
    mm_gemm<1><<<dim3(324, 1, 4), 256, DSMEM_REQ>>>(
        Hh + H_QWH, Hh + H_QWL, Hh + H_DTH, Hh + H_DTL, q,
        qb, nullptr, nullptr, nullptr, E_, N_, C_, 18, 18, 0, EN, EN);
    mm_gemm<1><<<dim3(324, 1, 4), 256, DSMEM_REQ>>>(
        Hh + H_KWH, Hh + H_KWL, Hh + H_DTH, Hh + H_DTL, k,
        kb, nullptr, nullptr, nullptr, E_, N_, C_, 18, 18, 0, EN, EN);
    mm_gemm<1><<<dim3(324, 1, 4), 256, DSMEM_REQ>>>(
        Hh + H_VWH, Hh + H_VWL, Hh + H_DTH, Hh + H_DTL, v,
        vb, nullptr, nullptr, nullptr, E_, N_, C_, 18, 18, 0, EN, EN);

    // attention
    split_plain<<<20736, 256>>>(q, Hh + H_QH, Hh + H_QL);
    split_plain<<<20736, 256>>>(k, Hh + H_KH, Hh + H_KL);
    transpose_split<<<dim3(72, 36, 4), 256>>>(v, Hh + H_VTH, Hh + H_VTL, E_, N_);
    mm_gemm<0><<<dim3(324, 1, 4), 256, DSMEM_REQ>>>(
        Hh + H_QH, Hh + H_QL, Hh + H_KH, Hh + H_KL, qk,
        nullptr, nullptr, nullptr, nullptr, E_, E_, N_, 18, 18, EN, EN, EN);
    softmax_bias<<<B_ * E_, 256>>>(qk, rel);
    split_plain<<<20736, 256>>>(qk, Hh + H_ATH, Hh + H_ATL);
    mm_gemm<0><<<dim3(324, 1, 4), 256, DSMEM_REQ>>>(
        Hh + H_ATH, Hh + H_ATL, Hh + H_VTH, Hh + H_VTL, ao,
        nullptr, nullptr, nullptr, nullptr, E_, N_, E_, 18, 18, EN, EN, EN);
    add_shuffle_ln<<<B_ * C_, 256>>>(ao, down, ln1g, ln1b, h1);

    // FFN
    split_plain<<<20736, 256>>>(h1, Hh + H_H1H, Hh + H_H1L);
    mm_gemm<2><<<dim3(2592, 1, 1), 256, DSMEM_REQ>>>(
        Hh + H_H1H, Hh + H_H1L, Hh + H_W1TH, Hh + H_W1TL, mid,
        fb1, nullptr, nullptr, nullptr, B_ * N_, E2, E_, 72, 36, 0, 0, 0);
    split_plain<<<41472, 256>>>(mid, Hh + H_MIDH, Hh + H_MIDL);
    mm_gemm<3><<<dim3(1296, 1, 1), 256, DSMEM_REQ>>>(
        Hh + H_MIDH, Hh + H_MIDL, Hh + H_W2TH, Hh + H_W2TL, ff,
        fb2, nullptr, nullptr, nullptr, B_ * N_, E_, E2, 72, 18, 0, 0, 0);
    add_ln<<<B_ * C_, 256>>>(ff, h1, ln2g, ln2b, outp);
    maxpool_k<<<20736, 256>>>(outp, pool);
}